// round 4
// baseline (speedup 1.0000x reference)
#include <cuda_runtime.h>
#include <cstdint>

#define THREADS 256
#define TILE 32
#define XSTR 196   // Xs row stride (192 + 4 pad)
#define HSTR 132   // Hs row stride (128 + 4 pad)

// ---- shared memory layout (floats) ----
constexpr int OFF_W1 = 0;            // 192*128 = 24576
constexpr int OFF_W2 = 24576;        // 128*128 = 16384
constexpr int OFF_X  = 40960;        // 32*196  = 6272
constexpr int OFF_H  = 47232;        // 32*132  = 4224
constexpr int OFF_RS = 51456;        // 8*32
constexpr int OFF_RQ = 51712;        // 8*32
constexpr int OFF_MU = 51968;        // 32
constexpr int OFF_SG = 52000;        // 32
constexpr int SMEM_FLOATS = 52032;   // 208128 bytes

__device__ __forceinline__ unsigned long long packf2(float x, float y) {
    unsigned long long r;
    asm("mov.b64 %0, {%1, %2};" : "=l"(r) : "f"(x), "f"(y));
    return r;
}
__device__ __forceinline__ void unpackf2(unsigned long long v, float& x, float& y) {
    asm("mov.b64 {%0, %1}, %2;" : "=f"(x), "=f"(y) : "l"(v));
}
__device__ __forceinline__ void fma2(unsigned long long& d, unsigned long long a, unsigned long long b) {
    asm("fma.rn.f32x2 %0, %1, %2, %0;" : "+l"(d) : "l"(a), "l"(b));
}
__device__ __forceinline__ float silu(float v) {
    return v / (1.0f + __expf(-v));
}

__global__ void __launch_bounds__(THREADS, 1)
edge_mlp_kernel(const float* __restrict__ src, const float* __restrict__ edg,
                const float* __restrict__ W1,  const float* __restrict__ b1,
                const float* __restrict__ gam, const float* __restrict__ bet,
                const float* __restrict__ W2,  const float* __restrict__ b2,
                float* __restrict__ out, int E, int ntiles)
{
    extern __shared__ float s[];
    float* W1s = s + OFF_W1;
    float* W2s = s + OFF_W2;
    float* Xs  = s + OFF_X;
    float* Hs  = s + OFF_H;
    float* RS  = s + OFF_RS;
    float* RQ  = s + OFF_RQ;
    float* MU  = s + OFF_MU;
    float* SG  = s + OFF_SG;

    const int tid  = threadIdx.x;
    const int warp = tid >> 5;
    const int lane = tid & 31;
    const int lc   = lane & 3;             // col-group within warp
    const int r4   = (lane >> 2) << 2;     // 4 rows (within tile)
    const int c4   = warp * 16 + lc * 4;   // 4 output cols

    // ---- stage weights into SMEM (once per block) ----
    {
        const float4* w1v = reinterpret_cast<const float4*>(W1);
        float4* w1s = reinterpret_cast<float4*>(W1s);
        #pragma unroll
        for (int i = 0; i < (24576 / 4) / THREADS; i++)
            w1s[tid + i * THREADS] = w1v[tid + i * THREADS];
        const float4* w2v = reinterpret_cast<const float4*>(W2);
        float4* w2s = reinterpret_cast<float4*>(W2s);
        #pragma unroll
        for (int i = 0; i < (16384 / 4) / THREADS; i++)
            w2s[tid + i * THREADS] = w2v[tid + i * THREADS];
    }
    // per-thread column constants
    float gg[4], be[4];
    unsigned long long b1p[2], b2p[2];
    {
        float t0 = b1[c4 + 0], t1 = b1[c4 + 1], t2 = b1[c4 + 2], t3 = b1[c4 + 3];
        b1p[0] = packf2(t0, t1); b1p[1] = packf2(t2, t3);
        t0 = b2[c4 + 0]; t1 = b2[c4 + 1]; t2 = b2[c4 + 2]; t3 = b2[c4 + 3];
        b2p[0] = packf2(t0, t1); b2p[1] = packf2(t2, t3);
        #pragma unroll
        for (int j = 0; j < 4; j++) { gg[j] = gam[c4 + j]; be[j] = bet[c4 + j]; }
    }
    __syncthreads();

    for (int tile = blockIdx.x; tile < ntiles; tile += gridDim.x) {
        const int row0 = tile * TILE;

        // ---- load x tile row-major: Xs[r][0:128)=src, [128:192)=edge ----
        // conflict-free: within a warp all lanes share r, c strides by 4 floats
        #pragma unroll
        for (int i = 0; i < 4; i++) {
            int idx = tid + i * THREADS;           // 1024 float4 of src
            int r = idx >> 5, c = (idx & 31) << 2;
            int rg = row0 + r; if (rg >= E) rg = E - 1;
            float4 v = *reinterpret_cast<const float4*>(src + (size_t)rg * 128 + c);
            *reinterpret_cast<float4*>(&Xs[r * XSTR + c]) = v;
        }
        #pragma unroll
        for (int i = 0; i < 2; i++) {
            int idx = tid + i * THREADS;           // 512 float4 of edge
            int r = idx >> 4, c = (idx & 15) << 2;
            int rg = row0 + r; if (rg >= E) rg = E - 1;
            float4 v = *reinterpret_cast<const float4*>(edg + (size_t)rg * 64 + c);
            *reinterpret_cast<float4*>(&Xs[r * XSTR + 128 + c]) = v;
        }
        __syncthreads();

        // ---- GEMM1: h[32][128] = x[32][192] @ W1 (packed f32x2) ----
        unsigned long long acc[4][2];
        #pragma unroll
        for (int i = 0; i < 4; i++) { acc[i][0] = b1p[0]; acc[i][1] = b1p[1]; }

        #pragma unroll 4
        for (int k = 0; k < 192; k += 2) {
            float2 x0 = *reinterpret_cast<const float2*>(&Xs[(r4 + 0) * XSTR + k]);
            float2 x1 = *reinterpret_cast<const float2*>(&Xs[(r4 + 1) * XSTR + k]);
            float2 x2 = *reinterpret_cast<const float2*>(&Xs[(r4 + 2) * XSTR + k]);
            float2 x3 = *reinterpret_cast<const float2*>(&Xs[(r4 + 3) * XSTR + k]);
            ulonglong2 wa = *reinterpret_cast<const ulonglong2*>(&W1s[k * 128 + c4]);
            ulonglong2 wb = *reinterpret_cast<const ulonglong2*>(&W1s[(k + 1) * 128 + c4]);
            unsigned long long d;
            d = packf2(x0.x, x0.x); fma2(acc[0][0], d, wa.x); fma2(acc[0][1], d, wa.y);
            d = packf2(x1.x, x1.x); fma2(acc[1][0], d, wa.x); fma2(acc[1][1], d, wa.y);
            d = packf2(x2.x, x2.x); fma2(acc[2][0], d, wa.x); fma2(acc[2][1], d, wa.y);
            d = packf2(x3.x, x3.x); fma2(acc[3][0], d, wa.x); fma2(acc[3][1], d, wa.y);
            d = packf2(x0.y, x0.y); fma2(acc[0][0], d, wb.x); fma2(acc[0][1], d, wb.y);
            d = packf2(x1.y, x1.y); fma2(acc[1][0], d, wb.x); fma2(acc[1][1], d, wb.y);
            d = packf2(x2.y, x2.y); fma2(acc[2][0], d, wb.x); fma2(acc[2][1], d, wb.y);
            d = packf2(x3.y, x3.y); fma2(acc[3][0], d, wb.x); fma2(acc[3][1], d, wb.y);
        }

        float h[4][4];
        #pragma unroll
        for (int i = 0; i < 4; i++) {
            unpackf2(acc[i][0], h[i][0], h[i][1]);
            unpackf2(acc[i][1], h[i][2], h[i][3]);
        }

        // ---- LayerNorm reductions: 4 col-groups/warp, 8 warps ----
        #pragma unroll
        for (int i = 0; i < 4; i++) {
            float sv = h[i][0] + h[i][1] + h[i][2] + h[i][3];
            float qv = h[i][0]*h[i][0] + h[i][1]*h[i][1] + h[i][2]*h[i][2] + h[i][3]*h[i][3];
            sv += __shfl_xor_sync(0xffffffffu, sv, 1);
            sv += __shfl_xor_sync(0xffffffffu, sv, 2);
            qv += __shfl_xor_sync(0xffffffffu, qv, 1);
            qv += __shfl_xor_sync(0xffffffffu, qv, 2);
            if (lc == 0) { RS[warp * 32 + r4 + i] = sv; RQ[warp * 32 + r4 + i] = qv; }
        }
        __syncthreads();
        if (tid < 32) {
            float ss = 0.f, qq = 0.f;
            #pragma unroll
            for (int w = 0; w < 8; w++) { ss += RS[w * 32 + tid]; qq += RQ[w * 32 + tid]; }
            float mu  = ss * (1.0f / 128.0f);
            float var = qq * (1.0f / 128.0f) - mu * mu;
            MU[tid] = mu;
            SG[tid] = rsqrtf(var + 1e-5f);
        }
        __syncthreads();

        // ---- normalize + SiLU -> Hs row-major ----
        #pragma unroll
        for (int i = 0; i < 4; i++) {
            float mu = MU[r4 + i], sg = SG[r4 + i];
            float4 t;
            t.x = silu((h[i][0] - mu) * sg * gg[0] + be[0]);
            t.y = silu((h[i][1] - mu) * sg * gg[1] + be[1]);
            t.z = silu((h[i][2] - mu) * sg * gg[2] + be[2]);
            t.w = silu((h[i][3] - mu) * sg * gg[3] + be[3]);
            *reinterpret_cast<float4*>(&Hs[(r4 + i) * HSTR + c4]) = t;
        }
        __syncthreads();

        // ---- GEMM2: o[32][128] = hsilu[32][128] @ W2 ----
        unsigned long long acc2[4][2];
        #pragma unroll
        for (int i = 0; i < 4; i++) { acc2[i][0] = b2p[0]; acc2[i][1] = b2p[1]; }

        #pragma unroll 4
        for (int k = 0; k < 128; k += 2) {
            float2 x0 = *reinterpret_cast<const float2*>(&Hs[(r4 + 0) * HSTR + k]);
            float2 x1 = *reinterpret_cast<const float2*>(&Hs[(r4 + 1) * HSTR + k]);
            float2 x2 = *reinterpret_cast<const float2*>(&Hs[(r4 + 2) * HSTR + k]);
            float2 x3 = *reinterpret_cast<const float2*>(&Hs[(r4 + 3) * HSTR + k]);
            ulonglong2 wa = *reinterpret_cast<const ulonglong2*>(&W2s[k * 128 + c4]);
            ulonglong2 wb = *reinterpret_cast<const ulonglong2*>(&W2s[(k + 1) * 128 + c4]);
            unsigned long long d;
            d = packf2(x0.x, x0.x); fma2(acc2[0][0], d, wa.x); fma2(acc2[0][1], d, wa.y);
            d = packf2(x1.x, x1.x); fma2(acc2[1][0], d, wa.x); fma2(acc2[1][1], d, wa.y);
            d = packf2(x2.x, x2.x); fma2(acc2[2][0], d, wa.x); fma2(acc2[2][1], d, wa.y);
            d = packf2(x3.x, x3.x); fma2(acc2[3][0], d, wa.x); fma2(acc2[3][1], d, wa.y);
            d = packf2(x0.y, x0.y); fma2(acc2[0][0], d, wb.x); fma2(acc2[0][1], d, wb.y);
            d = packf2(x1.y, x1.y); fma2(acc2[1][0], d, wb.x); fma2(acc2[1][1], d, wb.y);
            d = packf2(x2.y, x2.y); fma2(acc2[2][0], d, wb.x); fma2(acc2[2][1], d, wb.y);
            d = packf2(x3.y, x3.y); fma2(acc2[3][0], d, wb.x); fma2(acc2[3][1], d, wb.y);
        }

        // ---- SiLU + store ----
        #pragma unroll
        for (int i = 0; i < 4; i++) {
            float o0, o1, o2, o3;
            unpackf2(acc2[i][0], o0, o1);
            unpackf2(acc2[i][1], o2, o3);
            float4 t = make_float4(silu(o0), silu(o1), silu(o2), silu(o3));
            int rg = row0 + r4 + i;
            if (rg < E)
                *reinterpret_cast<float4*>(out + (size_t)rg * 128 + c4) = t;
        }

        __syncthreads();   // protect Xs/Hs/RS/RQ before next tile
    }
}

extern "C" void kernel_launch(void* const* d_in, const int* in_sizes, int n_in,
                              void* d_out, int out_size) {
    const float* src = (const float*)d_in[0];
    const float* edg = (const float*)d_in[1];
    const float* W1  = (const float*)d_in[2];
    const float* b1  = (const float*)d_in[3];
    const float* gam = (const float*)d_in[4];
    const float* bet = (const float*)d_in[5];
    const float* W2  = (const float*)d_in[6];
    const float* b2  = (const float*)d_in[7];
    float* out = (float*)d_out;

    int E = in_sizes[0] / 128;
    int ntiles = (E + TILE - 1) / TILE;

    static bool attr_set = false;
    if (!attr_set) {
        cudaFuncSetAttribute(edge_mlp_kernel,
                             cudaFuncAttributeMaxDynamicSharedMemorySize,
                             SMEM_FLOATS * sizeof(float));
        attr_set = true;
    }

    int grid = ntiles < 152 ? ntiles : 152;
    edge_mlp_kernel<<<grid, THREADS, SMEM_FLOATS * sizeof(float)>>>(
        src, edg, W1, b1, gam, bet, W2, b2, out, E, ntiles);
}